// round 15
// baseline (speedup 1.0000x reference)
#include <cuda_runtime.h>
#include <cuda_fp16.h>
#include <cstdint>

#define NMAX 100000
#define EMAX 1600000
#define HDIM 128
#define G3   384

// ---------------- scratch (device globals) ----------------
__device__ float g_deg[NMAX];
__device__ float g_dinv[NMAX];
__device__ int   g_cnt[NMAX];
__device__ int   g_rowptr[NMAX + 1];
__device__ int   g_cursor[NMAX];
__device__ int   g_bsum[256];
__device__ int   g_eidx[EMAX];
__device__ float g_enorm[EMAX];

// fp16 activations
__device__ __half g_x16[(size_t)NMAX * 128];
__device__ __half g_act[(size_t)NMAX * 128];
__device__ __half g_Y[(size_t)NMAX * 128];
__device__ __half g_hA16[(size_t)NMAX * 128];
__device__ __half g_hB16[(size_t)NMAX * 128];

// fp16 weights ([rows][128] K-major = B^T)
__device__ __half g_wlin[128 * 128];
__device__ __half g_wconv[3 * 128 * 128];
__device__ __half g_wih[G3 * 128];
__device__ __half g_whh[G3 * 128];
__device__ __half g_wfc[128 * 128];

// ---------------- mma/ldmatrix helpers ----------------
__device__ __forceinline__ uint32_t smem_u32(const void* p) {
    return (uint32_t)__cvta_generic_to_shared(p);
}
__device__ __forceinline__ void ldsm_x4(uint32_t& r0, uint32_t& r1, uint32_t& r2,
                                        uint32_t& r3, uint32_t addr) {
    asm volatile("ldmatrix.sync.aligned.m8n8.x4.shared.b16 {%0,%1,%2,%3}, [%4];"
                 : "=r"(r0), "=r"(r1), "=r"(r2), "=r"(r3) : "r"(addr));
}
__device__ __forceinline__ void mma_f16(float* d, const uint32_t* a, uint32_t b0, uint32_t b1) {
    asm volatile(
        "mma.sync.aligned.m16n8k16.row.col.f32.f16.f16.f32 "
        "{%0,%1,%2,%3}, {%4,%5,%6,%7}, {%8,%9}, {%0,%1,%2,%3};"
        : "+f"(d[0]), "+f"(d[1]), "+f"(d[2]), "+f"(d[3])
        : "r"(a[0]), "r"(a[1]), "r"(a[2]), "r"(a[3]), "r"(b0), "r"(b1));
}
__device__ __forceinline__ uint32_t swz(int row, int chunk) {
    return (uint32_t)(row * 256 + ((chunk ^ (row & 7)) << 4));
}
__device__ __forceinline__ float fast_sigmoid(float x) {
    return __fdividef(1.0f, 1.0f + __expf(-x));
}
__device__ __forceinline__ float fast_tanh(float x) {
    float y;
    asm("tanh.approx.f32 %0, %1;" : "=f"(y) : "f"(x));
    return y;
}

// ---------------- graph prep kernels ----------------
__global__ void init_deg_kernel(float* __restrict__ deg, int* __restrict__ cnt, int n) {
    int i = blockIdx.x * blockDim.x + threadIdx.x;
    if (i < n) { deg[i] = 1.0f; cnt[i] = 0; }
}
__global__ void deg_accum_kernel(const int* __restrict__ dst, const float* __restrict__ ew,
                                 float* __restrict__ deg, int* __restrict__ cnt, int E) {
    int e = blockIdx.x * blockDim.x + threadIdx.x;
    if (e < E) {
        int d = dst[e];
        atomicAdd(&deg[d], ew[e]);
        atomicAdd(&cnt[d], 1);
    }
}
__global__ void dinv_kernel(const float* __restrict__ deg, float* __restrict__ dinv, int n) {
    int i = blockIdx.x * blockDim.x + threadIdx.x;
    if (i < n) {
        float d = deg[i];
        dinv[i] = (d > 0.0f) ? rsqrtf(d) : 0.0f;
    }
}
__global__ void scan_block(const int* __restrict__ cnt, int* __restrict__ out,
                           int* __restrict__ bsum, int n) {
    __shared__ int sm[1024];
    int tx = threadIdx.x;
    int gid = blockIdx.x * 1024 + tx;
    int v = (gid < n) ? cnt[gid] : 0;
    sm[tx] = v;
    __syncthreads();
    for (int off = 1; off < 1024; off <<= 1) {
        int t = (tx >= off) ? sm[tx - off] : 0;
        __syncthreads();
        sm[tx] += t;
        __syncthreads();
    }
    if (gid < n) out[gid] = sm[tx] - v;
    if (tx == 1023) bsum[blockIdx.x] = sm[1023];
}
__global__ void scan_tops(int* __restrict__ bsum, int nb) {
    if (threadIdx.x == 0) {
        int acc = 0;
        for (int i = 0; i < nb; i++) { int v = bsum[i]; bsum[i] = acc; acc += v; }
    }
}
__global__ void scan_add(int* __restrict__ rowptr, int* __restrict__ cursor,
                         const int* __restrict__ bsum, int n, int E) {
    int gid = blockIdx.x * 1024 + threadIdx.x;
    if (gid < n) {
        int v = rowptr[gid] + bsum[blockIdx.x];
        rowptr[gid] = v;
        cursor[gid] = v;
    }
    if (gid == 0) rowptr[n] = E;
}
__global__ void fill_kernel(const int* __restrict__ src, const int* __restrict__ dst,
                            const float* __restrict__ ew, const float* __restrict__ dinv,
                            int* __restrict__ cursor, int* __restrict__ eidx,
                            float* __restrict__ enorm, int E) {
    int e = blockIdx.x * blockDim.x + threadIdx.x;
    if (e >= E) return;
    int s = src[e], d = dst[e];
    float nm = dinv[s] * ew[e] * dinv[d];
    int pos = atomicAdd(&cursor[d], 1);
    eidx[pos] = s;
    enorm[pos] = nm;
}

// ---------------- consolidated converts ----------------
__global__ void prep_weights(
    const float* __restrict__ linW, const float* __restrict__ convW,
    const float* __restrict__ Wih, const float* __restrict__ Whh,
    const float* __restrict__ fcW, int C,
    __half* __restrict__ wlin, __half* __restrict__ wconv,
    __half* __restrict__ wih, __half* __restrict__ whh, __half* __restrict__ wfc)
{
    int idx = blockIdx.x * blockDim.x + threadIdx.x;
    if (idx < 16384) {
        int n = idx >> 7, k = idx & 127;
        wlin[idx] = __float2half_rn(linW[(size_t)k * 128 + n]);        // trans
    } else if (idx < 65536) {
        int i = idx - 16384;
        int l = i >> 14, r = i & 16383;
        int n = r >> 7, k = r & 127;
        wconv[i] = __float2half_rn(convW[(size_t)l * 16384 + (size_t)k * 128 + n]);
    } else if (idx < 114688) {
        int i = idx - 65536;
        wih[i] = __float2half_rn(Wih[i]);                              // no trans
    } else if (idx < 163840) {
        int i = idx - 114688;
        whh[i] = __float2half_rn(Whh[i]);
    } else if (idx < 180224) {
        int i = idx - 163840;
        int n = i >> 7, k = i & 127;
        float v = (n < C) ? fcW[(size_t)k * C + n] : 0.0f;
        wfc[i] = __float2half_rn(v);
    }
}
__global__ void prep_acts(const float* __restrict__ x, const float* __restrict__ h0,
                          __half* __restrict__ x16, __half* __restrict__ hA, int n) {
    int i = blockIdx.x * blockDim.x + threadIdx.x;
    if (i < n) {
        x16[i] = __float2half_rn(x[i]);
        hA[i] = __float2half_rn(h0[i]);
    }
}

// ---------------- fp16 GEMM: C[M,Nc] = A[M,128] @ B^T (+bias)(+relu) ----------------
#define GF_A 0
#define GF_B 32768
#define GEMM_SMEM 65536

template <int RELU, int OUT>   // OUT: 0 = fp32 C[M,Nc], 1 = fp16 act[M,128]
__global__ __launch_bounds__(256, 2) void gemm_f16(
    const __half* __restrict__ A, const __half* __restrict__ B,
    const float* __restrict__ bias,
    float* __restrict__ C, __half* __restrict__ Cact,
    int M, int Nc)
{
    extern __shared__ char sm[];
    __shared__ float s_bias[128];
    const uint32_t smb = smem_u32(sm);
    const int tid = threadIdx.x;
    const int lane = tid & 31;
    const int wid = tid >> 5;
    const int m0 = blockIdx.y << 7;
    const int n0 = blockIdx.x << 7;

    for (int i = tid; i < 2048; i += 256) {
        int r = i >> 4, c = i & 15;
        uint4 v = make_uint4(0, 0, 0, 0);
        if (m0 + r < M) v = *(const uint4*)(A + (size_t)(m0 + r) * 128 + c * 8);
        *(uint4*)(sm + GF_A + swz(r, c)) = v;
    }
    for (int i = tid; i < 2048; i += 256) {
        int r = i >> 4, c = i & 15;
        uint4 v = *(const uint4*)(B + (size_t)(n0 + r) * 128 + c * 8);
        *(uint4*)(sm + GF_B + swz(r, c)) = v;
    }
    if (tid < 128) {
        int gn = n0 + tid;
        s_bias[tid] = (bias && gn < Nc) ? bias[gn] : 0.0f;
    }
    __syncthreads();

    const int wm = (wid >> 2) << 6;
    const int wn = (wid & 3) << 5;

    float acc[4][4][4];
#pragma unroll
    for (int i = 0; i < 4; i++)
#pragma unroll
        for (int j = 0; j < 4; j++)
#pragma unroll
            for (int k = 0; k < 4; k++) acc[i][j][k] = 0.0f;

#pragma unroll
    for (int kk = 0; kk < 8; kk++) {
        uint32_t bfr[2][4];
#pragma unroll
        for (int np = 0; np < 2; np++) {
            int row = wn + np * 16 + (lane & 15);
            int chunk = kk * 2 + (lane >> 4);
            ldsm_x4(bfr[np][0], bfr[np][1], bfr[np][2], bfr[np][3],
                    smb + GF_B + swz(row, chunk));
        }
#pragma unroll
        for (int mf = 0; mf < 4; mf++) {
            int row = wm + mf * 16 + (lane & 15);
            int chunk = kk * 2 + (lane >> 4);
            uint32_t a[4];
            ldsm_x4(a[0], a[1], a[2], a[3], smb + GF_A + swz(row, chunk));
#pragma unroll
            for (int nf = 0; nf < 4; nf++) {
                uint32_t b0 = bfr[nf >> 1][nf & 1];
                uint32_t b1 = bfr[nf >> 1][2 + (nf & 1)];
                mma_f16(acc[mf][nf], a, b0, b1);
            }
        }
    }

    const int gr = lane >> 2, gc = lane & 3;
#pragma unroll
    for (int mf = 0; mf < 4; mf++) {
#pragma unroll
        for (int i2 = 0; i2 < 2; i2++) {
            int r0 = m0 + wm + mf * 16 + gr + i2 * 8;
            if (r0 >= M) continue;
#pragma unroll
            for (int nf = 0; nf < 4; nf++) {
                int cl = wn + nf * 8 + (gc << 1);
                int col = n0 + cl;
                float v0 = acc[mf][nf][i2 * 2 + 0] + s_bias[cl];
                float v1 = acc[mf][nf][i2 * 2 + 1] + s_bias[cl + 1];
                if (RELU) { v0 = fmaxf(v0, 0.f); v1 = fmaxf(v1, 0.f); }
                if (OUT == 0) {
                    if (col < Nc) {
                        if (col + 1 < Nc)
                            *(float2*)(C + (size_t)r0 * Nc + col) = make_float2(v0, v1);
                        else
                            C[(size_t)r0 * Nc + col] = v0;
                    }
                } else {
                    *(__half2*)(Cact + (size_t)r0 * 128 + col) = __floats2half2_rn(v0, v1);
                }
            }
        }
    }
}

// ---------------- fused GRU + aggregate (block-level specialization) ----------------
// grid (2, nGruY + nAggY), 256 threads, 80KB dyn smem, 2 CTAs/SM.
//   by <  nGruY : GRU path (identical to validated gru_f16 2-phase kernel)
//   by >= nGruY : aggregate path; agg slice covers 64 nodes (2 blocks x 8 warps x 4)
#define GR_X 0
#define GR_P 16384
#define GR_W 32768
#define GRU_SMEM 81920

__global__ __launch_bounds__(256, 2) void gru_agg_f16(
    const __half* __restrict__ X, const __half* __restrict__ P,
    const __half* __restrict__ Wih, const __half* __restrict__ Whh,
    const float* __restrict__ bih, const float* __restrict__ bhh,
    __half* __restrict__ O, int M, int nGruY,
    const int* __restrict__ rowptr, const int* __restrict__ eidx,
    const float* __restrict__ enorm, const __half* __restrict__ Xa,
    const float* __restrict__ dinv, __half* __restrict__ Y, int do_agg)
{
    extern __shared__ char sm[];
    __shared__ float s_brz[128], s_bin[64], s_bhn[64];
    const int tid = threadIdx.x;
    const int lane = tid & 31;
    const int wid = tid >> 5;

    if ((int)blockIdx.y >= nGruY) {
        // ================= aggregate path =================
        if (!do_agg) return;
        int ab = ((int)blockIdx.y - nGruY) * 2 + (int)blockIdx.x;
        int wglobal = ab * 8 + wid;
#pragma unroll
        for (int nn = 0; nn < 4; nn++) {
            int node = wglobal * 4 + nn;
            if (node >= M) continue;
            int start = __ldg(rowptr + node);
            int end = __ldg(rowptr + node + 1);
            float a0 = 0.f, a1 = 0.f, a2 = 0.f, a3 = 0.f;
            int j = start;
            for (; j + 4 <= end; j += 4) {
                int s0 = __ldg(eidx + j);
                int s1 = __ldg(eidx + j + 1);
                int s2 = __ldg(eidx + j + 2);
                int s3 = __ldg(eidx + j + 3);
                float n0 = __ldg(enorm + j);
                float n1 = __ldg(enorm + j + 1);
                float n2 = __ldg(enorm + j + 2);
                float n3 = __ldg(enorm + j + 3);
                uint2 u0 = *(const uint2*)(Xa + (size_t)s0 * 128 + (lane << 2));
                uint2 u1 = *(const uint2*)(Xa + (size_t)s1 * 128 + (lane << 2));
                uint2 u2 = *(const uint2*)(Xa + (size_t)s2 * 128 + (lane << 2));
                uint2 u3 = *(const uint2*)(Xa + (size_t)s3 * 128 + (lane << 2));
                float2 p0a = __half22float2(*(__half2*)&u0.x), p0b = __half22float2(*(__half2*)&u0.y);
                float2 p1a = __half22float2(*(__half2*)&u1.x), p1b = __half22float2(*(__half2*)&u1.y);
                float2 p2a = __half22float2(*(__half2*)&u2.x), p2b = __half22float2(*(__half2*)&u2.y);
                float2 p3a = __half22float2(*(__half2*)&u3.x), p3b = __half22float2(*(__half2*)&u3.y);
                a0 += p0a.x * n0 + p1a.x * n1 + p2a.x * n2 + p3a.x * n3;
                a1 += p0a.y * n0 + p1a.y * n1 + p2a.y * n2 + p3a.y * n3;
                a2 += p0b.x * n0 + p1b.x * n1 + p2b.x * n2 + p3b.x * n3;
                a3 += p0b.y * n0 + p1b.y * n1 + p2b.y * n2 + p3b.y * n3;
            }
            for (; j < end; j++) {
                int s = __ldg(eidx + j);
                float nm = __ldg(enorm + j);
                uint2 u = *(const uint2*)(Xa + (size_t)s * 128 + (lane << 2));
                float2 pa = __half22float2(*(__half2*)&u.x), pb = __half22float2(*(__half2*)&u.y);
                a0 += pa.x * nm; a1 += pa.y * nm; a2 += pb.x * nm; a3 += pb.y * nm;
            }
            float di = __ldg(dinv + node);
            float sw = di * di;
            uint2 us = *(const uint2*)(Xa + (size_t)node * 128 + (lane << 2));
            float2 sa = __half22float2(*(__half2*)&us.x), sb = __half22float2(*(__half2*)&us.y);
            a0 += sa.x * sw; a1 += sa.y * sw; a2 += sb.x * sw; a3 += sb.y * sw;
            uint2 outv;
            *(__half2*)&outv.x = __floats2half2_rn(a0, a1);
            *(__half2*)&outv.y = __floats2half2_rn(a2, a3);
            *(uint2*)(Y + (size_t)node * 128 + (lane << 2)) = outv;
        }
        return;
    }

    // ================= GRU path =================
    const uint32_t smb = smem_u32(sm);
    const int m0 = (int)blockIdx.y << 6;
    const int n0 = (int)blockIdx.x << 6;

    for (int i = tid; i < 1024; i += 256) {
        int r = i >> 4, c = i & 15;
        uint4 xv = make_uint4(0, 0, 0, 0), pv = xv;
        if (m0 + r < M) {
            xv = *(const uint4*)(X + (size_t)(m0 + r) * 128 + c * 8);
            pv = *(const uint4*)(P + (size_t)(m0 + r) * 128 + c * 8);
        }
        uint32_t off = swz(r, c);
        *(uint4*)(sm + GR_X + off) = xv;
        *(uint4*)(sm + GR_P + off) = pv;
    }
    if (tid < 128) {
        int g = tid >> 6, c = tid & 63;
        s_brz[tid] = bih[g * 128 + n0 + c] + bhh[g * 128 + n0 + c];
    } else if (tid < 192) {
        int c = tid - 128;
        s_bin[c] = bih[256 + n0 + c];
        s_bhn[c] = bhh[256 + n0 + c];
    }

    const int wm = (wid & 1) << 5;
    const int wn = (wid >> 1) << 4;

    // acc slots: 0=r (shared), 1=z (shared), 2=in (Wih·X), 3=hn (Whh·P)
    float acc[4][2][2][4];
#pragma unroll
    for (int s = 0; s < 4; s++)
#pragma unroll
        for (int i = 0; i < 2; i++)
#pragma unroll
            for (int j = 0; j < 2; j++)
#pragma unroll
                for (int k = 0; k < 4; k++) acc[s][i][j][k] = 0.0f;

#pragma unroll
    for (int ph = 0; ph < 2; ph++) {
        const __half* W = ph ? Whh : Wih;
        const uint32_t aP = ph ? GR_P : GR_X;

        __syncthreads();
        for (int i = tid; i < 3072; i += 256) {
            int g = i >> 10;
            int r = (i >> 4) & 63;
            int c = i & 15;
            int grow = g * 128 + n0 + r;
            uint4 v = *(const uint4*)(W + (size_t)grow * 128 + c * 8);
            *(uint4*)(sm + GR_W + g * 16384 + swz(r, c)) = v;
        }
        __syncthreads();

#pragma unroll
        for (int kk = 0; kk < 8; kk++) {
            uint32_t bfr[3][4];
#pragma unroll
            for (int g = 0; g < 3; g++) {
                int row = wn + (lane & 15);
                int chunk = kk * 2 + (lane >> 4);
                ldsm_x4(bfr[g][0], bfr[g][1], bfr[g][2], bfr[g][3],
                        smb + GR_W + g * 16384 + swz(row, chunk));
            }
#pragma unroll
            for (int mf = 0; mf < 2; mf++) {
                int row = wm + mf * 16 + (lane & 15);
                int chunk = kk * 2 + (lane >> 4);
                uint32_t a[4];
                ldsm_x4(a[0], a[1], a[2], a[3], smb + aP + swz(row, chunk));
#pragma unroll
                for (int g = 0; g < 3; g++) {
                    int slot = (g < 2) ? g : (2 + ph);
#pragma unroll
                    for (int nf = 0; nf < 2; nf++)
                        mma_f16(acc[slot][mf][nf], a, bfr[g][nf], bfr[g][2 + nf]);
                }
            }
        }
    }

    const int gr = lane >> 2, gc = lane & 3;
#pragma unroll
    for (int mf = 0; mf < 2; mf++) {
#pragma unroll
        for (int i2 = 0; i2 < 2; i2++) {
            int lrow = wm + mf * 16 + gr + i2 * 8;
            int row = m0 + lrow;
            if (row >= M) continue;
#pragma unroll
            for (int nf = 0; nf < 2; nf++) {
                int cl = wn + nf * 8 + (gc << 1);
                int gcol = n0 + cl;
                float rr0 = acc[0][mf][nf][i2 * 2 + 0] + s_brz[cl];
                float rr1 = acc[0][mf][nf][i2 * 2 + 1] + s_brz[cl + 1];
                float zz0 = acc[1][mf][nf][i2 * 2 + 0] + s_brz[64 + cl];
                float zz1 = acc[1][mf][nf][i2 * 2 + 1] + s_brz[64 + cl + 1];
                float in0 = acc[2][mf][nf][i2 * 2 + 0] + s_bin[cl];
                float in1 = acc[2][mf][nf][i2 * 2 + 1] + s_bin[cl + 1];
                float hn0 = acc[3][mf][nf][i2 * 2 + 0] + s_bhn[cl];
                float hn1 = acc[3][mf][nf][i2 * 2 + 1] + s_bhn[cl + 1];
                uint32_t poff = swz(lrow, gcol >> 3) + (gcol & 7) * 2;
                __half2 hp2 = *(__half2*)(sm + GR_P + poff);
                float hp0 = __low2float(hp2), hp1 = __high2float(hp2);
                float r0 = fast_sigmoid(rr0);
                float r1 = fast_sigmoid(rr1);
                float z0 = fast_sigmoid(zz0);
                float z1 = fast_sigmoid(zz1);
                float n0v = fast_tanh(in0 + r0 * hn0);
                float n1v = fast_tanh(in1 + r1 * hn1);
                float h0 = (1.0f - z0) * n0v + z0 * hp0;
                float h1 = (1.0f - z1) * n1v + z1 * hp1;
                *(__half2*)(O + (size_t)row * 128 + gcol) = __floats2half2_rn(h0, h1);
            }
        }
    }
}

// ---------------- host launch ----------------
extern "C" void kernel_launch(void* const* d_in, const int* in_sizes, int n_in,
                              void* d_out, int out_size) {
    const float* x     = (const float*)d_in[0];
    const int*   ei    = (const int*)d_in[1];
    const float* ew    = (const float*)d_in[2];
    const float* h0    = (const float*)d_in[3];
    const float* linW  = (const float*)d_in[4];
    const float* linB  = (const float*)d_in[5];
    const float* convW = (const float*)d_in[6];
    const float* convB = (const float*)d_in[7];
    const float* Wih   = (const float*)d_in[8];
    const float* Whh   = (const float*)d_in[9];
    const float* bih   = (const float*)d_in[10];
    const float* bhh   = (const float*)d_in[11];
    const float* fcW   = (const float*)d_in[12];
    const float* fcB   = (const float*)d_in[13];
    float* out = (float*)d_out;

    const int N = in_sizes[0] / HDIM;
    const int E = in_sizes[2];
    const int C = in_sizes[13];  // 40
    const int* src = ei;
    const int* dst = ei + E;

    float *p_deg, *p_dinv, *p_enorm;
    int *p_cnt, *p_rowptr, *p_cursor, *p_bsum, *p_eidx;
    cudaGetSymbolAddress((void**)&p_deg, g_deg);
    cudaGetSymbolAddress((void**)&p_dinv, g_dinv);
    cudaGetSymbolAddress((void**)&p_cnt, g_cnt);
    cudaGetSymbolAddress((void**)&p_rowptr, g_rowptr);
    cudaGetSymbolAddress((void**)&p_cursor, g_cursor);
    cudaGetSymbolAddress((void**)&p_bsum, g_bsum);
    cudaGetSymbolAddress((void**)&p_eidx, g_eidx);
    cudaGetSymbolAddress((void**)&p_enorm, g_enorm);

    __half *p_x16, *p_act, *p_Y, *p_hA, *p_hB;
    cudaGetSymbolAddress((void**)&p_x16, g_x16);
    cudaGetSymbolAddress((void**)&p_act, g_act);
    cudaGetSymbolAddress((void**)&p_Y, g_Y);
    cudaGetSymbolAddress((void**)&p_hA, g_hA16);
    cudaGetSymbolAddress((void**)&p_hB, g_hB16);

    __half *w_lin, *w_conv, *w_ih, *w_hh, *w_fc;
    cudaGetSymbolAddress((void**)&w_lin, g_wlin);
    cudaGetSymbolAddress((void**)&w_conv, g_wconv);
    cudaGetSymbolAddress((void**)&w_ih, g_wih);
    cudaGetSymbolAddress((void**)&w_hh, g_whh);
    cudaGetSymbolAddress((void**)&w_fc, g_wfc);

    const int T = 256;
    auto cdiv = [](int a, int b) { return (a + b - 1) / b; };

    static bool attr_done = false;
    if (!attr_done) {
        cudaFuncSetAttribute(gemm_f16<1,1>, cudaFuncAttributeMaxDynamicSharedMemorySize, GEMM_SMEM);
        cudaFuncSetAttribute(gemm_f16<0,0>, cudaFuncAttributeMaxDynamicSharedMemorySize, GEMM_SMEM);
        cudaFuncSetAttribute(gru_agg_f16, cudaFuncAttributeMaxDynamicSharedMemorySize, GRU_SMEM);
        attr_done = true;
    }

    const int gy = cdiv(N, 128);    // 782
    const int gy64 = cdiv(N, 64);   // 1563 GRU y-blocks
    const int aggY = cdiv(N, 64);   // agg y-slices: 64 nodes per slice (2 blk x 8 warp x 4)

    // ---- consolidated prep ----
    prep_weights<<<cdiv(180224, T), T>>>(linW, convW, Wih, Whh, fcW, C,
                                         w_lin, w_conv, w_ih, w_hh, w_fc);
    prep_acts<<<cdiv(N * 128, T), T>>>(x, h0, p_x16, p_hA, N * 128);

    // ---- graph prep ----
    init_deg_kernel<<<cdiv(N, T), T>>>(p_deg, p_cnt, N);
    deg_accum_kernel<<<cdiv(E, T), T>>>(dst, ew, p_deg, p_cnt, E);
    dinv_kernel<<<cdiv(N, T), T>>>(p_deg, p_dinv, N);
    const int NB = cdiv(N, 1024);
    scan_block<<<NB, 1024>>>(p_cnt, p_rowptr, p_bsum, N);
    scan_tops<<<1, 32>>>(p_bsum, NB);
    scan_add<<<NB, 1024>>>(p_rowptr, p_cursor, p_bsum, N, E);
    fill_kernel<<<cdiv(E, T), T>>>(src, dst, ew, p_dinv, p_cursor, p_eidx, p_enorm, E);

    // lin: act = relu(x @ linW + linB)
    gemm_f16<1,1><<<dim3(1, gy), 256, GEMM_SMEM>>>(p_x16, w_lin, linB, nullptr, p_act, N, 128);

    // GRU 1 fused with aggregate_1(act)
    gru_agg_f16<<<dim3(2, gy64 + aggY), 256, GRU_SMEM>>>(
        p_act, p_hA, w_ih, w_hh, bih, bhh, p_hB, N, gy64,
        p_rowptr, p_eidx, p_enorm, p_act, p_dinv, p_Y, 1);

    __half *cur = p_hB, *nxt = p_hA;

    // 3 GCN layers; GRU_l fused with aggregate_{l+1} (except after last conv)
    for (int l = 0; l < 3; l++) {
        gemm_f16<1,1><<<dim3(1, gy), 256, GEMM_SMEM>>>(p_Y, w_conv + (size_t)l * 16384,
            convB + (size_t)l * HDIM, nullptr, p_act, N, 128);
        int more = (l < 2);
        gru_agg_f16<<<dim3(2, gy64 + (more ? aggY : 0)), 256, GRU_SMEM>>>(
            p_act, cur, w_ih, w_hh, bih, bhh, nxt, N, gy64,
            p_rowptr, p_eidx, p_enorm, p_act, p_dinv, p_Y, more);
        __half* t = cur; cur = nxt; nxt = t;
    }

    // out = h @ fcW + fcB
    gemm_f16<0,0><<<dim3(1, gy), 256, GEMM_SMEM>>>(cur, w_fc, fcB, out, nullptr, N, C);
}

// round 16
// speedup vs baseline: 1.2474x; 1.2474x over previous
#include <cuda_runtime.h>
#include <cuda_fp16.h>
#include <cstdint>

#define NMAX 100000
#define EMAX 1600000
#define HDIM 128
#define G3   384

// ---------------- scratch (device globals) ----------------
__device__ float g_deg[NMAX];
__device__ float g_dinv[NMAX];
__device__ int   g_cnt[NMAX];
__device__ int   g_rowptr[NMAX + 1];
__device__ int   g_cursor[NMAX];
__device__ int   g_bsum[256];
__device__ int   g_eidx[EMAX];
__device__ float g_enorm[EMAX];

// fp16 activations
__device__ __half g_x16[(size_t)NMAX * 128];
__device__ __half g_act[(size_t)NMAX * 128];
__device__ __half g_Y[(size_t)NMAX * 128];
__device__ __half g_hA16[(size_t)NMAX * 128];
__device__ __half g_hB16[(size_t)NMAX * 128];

// fp16 weights ([rows][128] K-major = B^T)
__device__ __half g_wlin[128 * 128];
__device__ __half g_wconv[3 * 128 * 128];
__device__ __half g_wih[G3 * 128];
__device__ __half g_whh[G3 * 128];
__device__ __half g_wfc[128 * 128];

// ---------------- mma/ldmatrix helpers ----------------
__device__ __forceinline__ uint32_t smem_u32(const void* p) {
    return (uint32_t)__cvta_generic_to_shared(p);
}
__device__ __forceinline__ void ldsm_x4(uint32_t& r0, uint32_t& r1, uint32_t& r2,
                                        uint32_t& r3, uint32_t addr) {
    asm volatile("ldmatrix.sync.aligned.m8n8.x4.shared.b16 {%0,%1,%2,%3}, [%4];"
                 : "=r"(r0), "=r"(r1), "=r"(r2), "=r"(r3) : "r"(addr));
}
__device__ __forceinline__ void mma_f16(float* d, const uint32_t* a, uint32_t b0, uint32_t b1) {
    asm volatile(
        "mma.sync.aligned.m16n8k16.row.col.f32.f16.f16.f32 "
        "{%0,%1,%2,%3}, {%4,%5,%6,%7}, {%8,%9}, {%0,%1,%2,%3};"
        : "+f"(d[0]), "+f"(d[1]), "+f"(d[2]), "+f"(d[3])
        : "r"(a[0]), "r"(a[1]), "r"(a[2]), "r"(a[3]), "r"(b0), "r"(b1));
}
__device__ __forceinline__ uint32_t swz(int row, int chunk) {
    return (uint32_t)(row * 256 + ((chunk ^ (row & 7)) << 4));
}
__device__ __forceinline__ float fast_sigmoid(float x) {
    return __fdividef(1.0f, 1.0f + __expf(-x));
}
__device__ __forceinline__ float fast_tanh(float x) {
    float y;
    asm("tanh.approx.f32 %0, %1;" : "=f"(y) : "f"(x));
    return y;
}

// ---------------- graph prep kernels ----------------
__global__ void init_deg_kernel(float* __restrict__ deg, int* __restrict__ cnt, int n) {
    int i = blockIdx.x * blockDim.x + threadIdx.x;
    if (i < n) { deg[i] = 1.0f; cnt[i] = 0; }
}
__global__ void deg_accum_kernel(const int* __restrict__ dst, const float* __restrict__ ew,
                                 float* __restrict__ deg, int* __restrict__ cnt, int E) {
    int e = blockIdx.x * blockDim.x + threadIdx.x;
    if (e < E) {
        int d = dst[e];
        atomicAdd(&deg[d], ew[e]);
        atomicAdd(&cnt[d], 1);
    }
}
__global__ void dinv_kernel(const float* __restrict__ deg, float* __restrict__ dinv, int n) {
    int i = blockIdx.x * blockDim.x + threadIdx.x;
    if (i < n) {
        float d = deg[i];
        dinv[i] = (d > 0.0f) ? rsqrtf(d) : 0.0f;
    }
}
__global__ void scan_block(const int* __restrict__ cnt, int* __restrict__ out,
                           int* __restrict__ bsum, int n) {
    __shared__ int sm[1024];
    int tx = threadIdx.x;
    int gid = blockIdx.x * 1024 + tx;
    int v = (gid < n) ? cnt[gid] : 0;
    sm[tx] = v;
    __syncthreads();
    for (int off = 1; off < 1024; off <<= 1) {
        int t = (tx >= off) ? sm[tx - off] : 0;
        __syncthreads();
        sm[tx] += t;
        __syncthreads();
    }
    if (gid < n) out[gid] = sm[tx] - v;
    if (tx == 1023) bsum[blockIdx.x] = sm[1023];
}
__global__ void scan_tops(int* __restrict__ bsum, int nb) {
    if (threadIdx.x == 0) {
        int acc = 0;
        for (int i = 0; i < nb; i++) { int v = bsum[i]; bsum[i] = acc; acc += v; }
    }
}
__global__ void scan_add(int* __restrict__ rowptr, int* __restrict__ cursor,
                         const int* __restrict__ bsum, int n, int E) {
    int gid = blockIdx.x * 1024 + threadIdx.x;
    if (gid < n) {
        int v = rowptr[gid] + bsum[blockIdx.x];
        rowptr[gid] = v;
        cursor[gid] = v;
    }
    if (gid == 0) rowptr[n] = E;
}
__global__ void fill_kernel(const int* __restrict__ src, const int* __restrict__ dst,
                            const float* __restrict__ ew, const float* __restrict__ dinv,
                            int* __restrict__ cursor, int* __restrict__ eidx,
                            float* __restrict__ enorm, int E) {
    int e = blockIdx.x * blockDim.x + threadIdx.x;
    if (e >= E) return;
    int s = src[e], d = dst[e];
    float nm = dinv[s] * ew[e] * dinv[d];
    int pos = atomicAdd(&cursor[d], 1);
    eidx[pos] = s;
    enorm[pos] = nm;
}

// ---------------- consolidated converts ----------------
__global__ void prep_weights(
    const float* __restrict__ linW, const float* __restrict__ convW,
    const float* __restrict__ Wih, const float* __restrict__ Whh,
    const float* __restrict__ fcW, int C,
    __half* __restrict__ wlin, __half* __restrict__ wconv,
    __half* __restrict__ wih, __half* __restrict__ whh, __half* __restrict__ wfc)
{
    int idx = blockIdx.x * blockDim.x + threadIdx.x;
    if (idx < 16384) {
        int n = idx >> 7, k = idx & 127;
        wlin[idx] = __float2half_rn(linW[(size_t)k * 128 + n]);        // trans
    } else if (idx < 65536) {
        int i = idx - 16384;
        int l = i >> 14, r = i & 16383;
        int n = r >> 7, k = r & 127;
        wconv[i] = __float2half_rn(convW[(size_t)l * 16384 + (size_t)k * 128 + n]);
    } else if (idx < 114688) {
        int i = idx - 65536;
        wih[i] = __float2half_rn(Wih[i]);                              // no trans
    } else if (idx < 163840) {
        int i = idx - 114688;
        whh[i] = __float2half_rn(Whh[i]);
    } else if (idx < 180224) {
        int i = idx - 163840;
        int n = i >> 7, k = i & 127;
        float v = (n < C) ? fcW[(size_t)k * C + n] : 0.0f;
        wfc[i] = __float2half_rn(v);
    }
}
__global__ void prep_acts(const float* __restrict__ x, const float* __restrict__ h0,
                          __half* __restrict__ x16, __half* __restrict__ hA, int n) {
    int i = blockIdx.x * blockDim.x + threadIdx.x;
    if (i < n) {
        x16[i] = __float2half_rn(x[i]);
        hA[i] = __float2half_rn(h0[i]);
    }
}

// ---------------- fp16 GEMM: C[M,Nc] = A[M,128] @ B^T (+bias)(+relu) ----------------
#define GF_A 0
#define GF_B 32768
#define GEMM_SMEM 65536

template <int RELU, int OUT>   // OUT: 0 = fp32 C[M,Nc], 1 = fp16 act[M,128]
__global__ __launch_bounds__(256, 2) void gemm_f16(
    const __half* __restrict__ A, const __half* __restrict__ B,
    const float* __restrict__ bias,
    float* __restrict__ C, __half* __restrict__ Cact,
    int M, int Nc)
{
    extern __shared__ char sm[];
    __shared__ float s_bias[128];
    const uint32_t smb = smem_u32(sm);
    const int tid = threadIdx.x;
    const int lane = tid & 31;
    const int wid = tid >> 5;
    const int m0 = blockIdx.y << 7;
    const int n0 = blockIdx.x << 7;

    for (int i = tid; i < 2048; i += 256) {
        int r = i >> 4, c = i & 15;
        uint4 v = make_uint4(0, 0, 0, 0);
        if (m0 + r < M) v = *(const uint4*)(A + (size_t)(m0 + r) * 128 + c * 8);
        *(uint4*)(sm + GF_A + swz(r, c)) = v;
    }
    for (int i = tid; i < 2048; i += 256) {
        int r = i >> 4, c = i & 15;
        uint4 v = *(const uint4*)(B + (size_t)(n0 + r) * 128 + c * 8);
        *(uint4*)(sm + GF_B + swz(r, c)) = v;
    }
    if (tid < 128) {
        int gn = n0 + tid;
        s_bias[tid] = (bias && gn < Nc) ? bias[gn] : 0.0f;
    }
    __syncthreads();

    const int wm = (wid >> 2) << 6;
    const int wn = (wid & 3) << 5;

    float acc[4][4][4];
#pragma unroll
    for (int i = 0; i < 4; i++)
#pragma unroll
        for (int j = 0; j < 4; j++)
#pragma unroll
            for (int k = 0; k < 4; k++) acc[i][j][k] = 0.0f;

#pragma unroll
    for (int kk = 0; kk < 8; kk++) {
        uint32_t bfr[2][4];
#pragma unroll
        for (int np = 0; np < 2; np++) {
            int row = wn + np * 16 + (lane & 15);
            int chunk = kk * 2 + (lane >> 4);
            ldsm_x4(bfr[np][0], bfr[np][1], bfr[np][2], bfr[np][3],
                    smb + GF_B + swz(row, chunk));
        }
#pragma unroll
        for (int mf = 0; mf < 4; mf++) {
            int row = wm + mf * 16 + (lane & 15);
            int chunk = kk * 2 + (lane >> 4);
            uint32_t a[4];
            ldsm_x4(a[0], a[1], a[2], a[3], smb + GF_A + swz(row, chunk));
#pragma unroll
            for (int nf = 0; nf < 4; nf++) {
                uint32_t b0 = bfr[nf >> 1][nf & 1];
                uint32_t b1 = bfr[nf >> 1][2 + (nf & 1)];
                mma_f16(acc[mf][nf], a, b0, b1);
            }
        }
    }

    const int gr = lane >> 2, gc = lane & 3;
#pragma unroll
    for (int mf = 0; mf < 4; mf++) {
#pragma unroll
        for (int i2 = 0; i2 < 2; i2++) {
            int r0 = m0 + wm + mf * 16 + gr + i2 * 8;
            if (r0 >= M) continue;
#pragma unroll
            for (int nf = 0; nf < 4; nf++) {
                int cl = wn + nf * 8 + (gc << 1);
                int col = n0 + cl;
                float v0 = acc[mf][nf][i2 * 2 + 0] + s_bias[cl];
                float v1 = acc[mf][nf][i2 * 2 + 1] + s_bias[cl + 1];
                if (RELU) { v0 = fmaxf(v0, 0.f); v1 = fmaxf(v1, 0.f); }
                if (OUT == 0) {
                    if (col < Nc) {
                        if (col + 1 < Nc)
                            *(float2*)(C + (size_t)r0 * Nc + col) = make_float2(v0, v1);
                        else
                            C[(size_t)r0 * Nc + col] = v0;
                    }
                } else {
                    *(__half2*)(Cact + (size_t)r0 * 128 + col) = __floats2half2_rn(v0, v1);
                }
            }
        }
    }
}

// ---------------- fused GRU fp16, 2-phase (validated R13 version) ----------------
#define GR_X 0
#define GR_P 16384
#define GR_W 32768
#define GRU_SMEM 81920

__global__ __launch_bounds__(256, 2) void gru_f16(
    const __half* __restrict__ X, const __half* __restrict__ P,
    const __half* __restrict__ Wih, const __half* __restrict__ Whh,
    const float* __restrict__ bih, const float* __restrict__ bhh,
    __half* __restrict__ O, int M)
{
    extern __shared__ char sm[];
    __shared__ float s_brz[128], s_bin[64], s_bhn[64];
    const uint32_t smb = smem_u32(sm);
    const int tid = threadIdx.x;
    const int lane = tid & 31;
    const int wid = tid >> 5;
    const int m0 = blockIdx.y << 6;
    const int n0 = blockIdx.x << 6;

    for (int i = tid; i < 1024; i += 256) {
        int r = i >> 4, c = i & 15;
        uint4 xv = make_uint4(0, 0, 0, 0), pv = xv;
        if (m0 + r < M) {
            xv = *(const uint4*)(X + (size_t)(m0 + r) * 128 + c * 8);
            pv = *(const uint4*)(P + (size_t)(m0 + r) * 128 + c * 8);
        }
        uint32_t off = swz(r, c);
        *(uint4*)(sm + GR_X + off) = xv;
        *(uint4*)(sm + GR_P + off) = pv;
    }
    if (tid < 128) {
        int g = tid >> 6, c = tid & 63;
        s_brz[tid] = bih[g * 128 + n0 + c] + bhh[g * 128 + n0 + c];
    } else if (tid < 192) {
        int c = tid - 128;
        s_bin[c] = bih[256 + n0 + c];
        s_bhn[c] = bhh[256 + n0 + c];
    }

    const int wm = (wid & 1) << 5;
    const int wn = (wid >> 1) << 4;

    float acc[4][2][2][4];
#pragma unroll
    for (int s = 0; s < 4; s++)
#pragma unroll
        for (int i = 0; i < 2; i++)
#pragma unroll
            for (int j = 0; j < 2; j++)
#pragma unroll
                for (int k = 0; k < 4; k++) acc[s][i][j][k] = 0.0f;

#pragma unroll
    for (int ph = 0; ph < 2; ph++) {
        const __half* W = ph ? Whh : Wih;
        const uint32_t aP = ph ? GR_P : GR_X;

        __syncthreads();
        for (int i = tid; i < 3072; i += 256) {
            int g = i >> 10;
            int r = (i >> 4) & 63;
            int c = i & 15;
            int grow = g * 128 + n0 + r;
            uint4 v = *(const uint4*)(W + (size_t)grow * 128 + c * 8);
            *(uint4*)(sm + GR_W + g * 16384 + swz(r, c)) = v;
        }
        __syncthreads();

#pragma unroll
        for (int kk = 0; kk < 8; kk++) {
            uint32_t bfr[3][4];
#pragma unroll
            for (int g = 0; g < 3; g++) {
                int row = wn + (lane & 15);
                int chunk = kk * 2 + (lane >> 4);
                ldsm_x4(bfr[g][0], bfr[g][1], bfr[g][2], bfr[g][3],
                        smb + GR_W + g * 16384 + swz(row, chunk));
            }
#pragma unroll
            for (int mf = 0; mf < 2; mf++) {
                int row = wm + mf * 16 + (lane & 15);
                int chunk = kk * 2 + (lane >> 4);
                uint32_t a[4];
                ldsm_x4(a[0], a[1], a[2], a[3], smb + aP + swz(row, chunk));
#pragma unroll
                for (int g = 0; g < 3; g++) {
                    int slot = (g < 2) ? g : (2 + ph);
#pragma unroll
                    for (int nf = 0; nf < 2; nf++)
                        mma_f16(acc[slot][mf][nf], a, bfr[g][nf], bfr[g][2 + nf]);
                }
            }
        }
    }

    const int gr = lane >> 2, gc = lane & 3;
#pragma unroll
    for (int mf = 0; mf < 2; mf++) {
#pragma unroll
        for (int i2 = 0; i2 < 2; i2++) {
            int lrow = wm + mf * 16 + gr + i2 * 8;
            int row = m0 + lrow;
            if (row >= M) continue;
#pragma unroll
            for (int nf = 0; nf < 2; nf++) {
                int cl = wn + nf * 8 + (gc << 1);
                int gcol = n0 + cl;
                float rr0 = acc[0][mf][nf][i2 * 2 + 0] + s_brz[cl];
                float rr1 = acc[0][mf][nf][i2 * 2 + 1] + s_brz[cl + 1];
                float zz0 = acc[1][mf][nf][i2 * 2 + 0] + s_brz[64 + cl];
                float zz1 = acc[1][mf][nf][i2 * 2 + 1] + s_brz[64 + cl + 1];
                float in0 = acc[2][mf][nf][i2 * 2 + 0] + s_bin[cl];
                float in1 = acc[2][mf][nf][i2 * 2 + 1] + s_bin[cl + 1];
                float hn0 = acc[3][mf][nf][i2 * 2 + 0] + s_bhn[cl];
                float hn1 = acc[3][mf][nf][i2 * 2 + 1] + s_bhn[cl + 1];
                uint32_t poff = swz(lrow, gcol >> 3) + (gcol & 7) * 2;
                __half2 hp2 = *(__half2*)(sm + GR_P + poff);
                float hp0 = __low2float(hp2), hp1 = __high2float(hp2);
                float r0 = fast_sigmoid(rr0);
                float r1 = fast_sigmoid(rr1);
                float z0 = fast_sigmoid(zz0);
                float z1 = fast_sigmoid(zz1);
                float n0v = fast_tanh(in0 + r0 * hn0);
                float n1v = fast_tanh(in1 + r1 * hn1);
                float h0 = (1.0f - z0) * n0v + z0 * hp0;
                float h1 = (1.0f - z1) * n1v + z1 * hp1;
                *(__half2*)(O + (size_t)row * 128 + gcol) = __floats2half2_rn(h0, h1);
            }
        }
    }
}

// ---------------- CSR gather aggregation on fp16 activations (validated R13) ----------------
__global__ __launch_bounds__(256) void aggregate_f16(
    const int* __restrict__ rowptr, const int* __restrict__ eidx,
    const float* __restrict__ enorm, const __half* __restrict__ X,
    const float* __restrict__ dinv, __half* __restrict__ Y, int N)
{
    int node = (int)(((size_t)blockIdx.x * blockDim.x + threadIdx.x) >> 5);
    if (node >= N) return;
    int lane = threadIdx.x & 31;
    int start = __ldg(rowptr + node);
    int end = __ldg(rowptr + node + 1);
    float a0 = 0.f, a1 = 0.f, a2 = 0.f, a3 = 0.f;
    int j = start;
    for (; j + 4 <= end; j += 4) {
        int s0 = __ldg(eidx + j);
        int s1 = __ldg(eidx + j + 1);
        int s2 = __ldg(eidx + j + 2);
        int s3 = __ldg(eidx + j + 3);
        float n0 = __ldg(enorm + j);
        float n1 = __ldg(enorm + j + 1);
        float n2 = __ldg(enorm + j + 2);
        float n3 = __ldg(enorm + j + 3);
        uint2 u0 = *(const uint2*)(X + (size_t)s0 * 128 + (lane << 2));
        uint2 u1 = *(const uint2*)(X + (size_t)s1 * 128 + (lane << 2));
        uint2 u2 = *(const uint2*)(X + (size_t)s2 * 128 + (lane << 2));
        uint2 u3 = *(const uint2*)(X + (size_t)s3 * 128 + (lane << 2));
        float2 p0a = __half22float2(*(__half2*)&u0.x), p0b = __half22float2(*(__half2*)&u0.y);
        float2 p1a = __half22float2(*(__half2*)&u1.x), p1b = __half22float2(*(__half2*)&u1.y);
        float2 p2a = __half22float2(*(__half2*)&u2.x), p2b = __half22float2(*(__half2*)&u2.y);
        float2 p3a = __half22float2(*(__half2*)&u3.x), p3b = __half22float2(*(__half2*)&u3.y);
        a0 += p0a.x * n0 + p1a.x * n1 + p2a.x * n2 + p3a.x * n3;
        a1 += p0a.y * n0 + p1a.y * n1 + p2a.y * n2 + p3a.y * n3;
        a2 += p0b.x * n0 + p1b.x * n1 + p2b.x * n2 + p3b.x * n3;
        a3 += p0b.y * n0 + p1b.y * n1 + p2b.y * n2 + p3b.y * n3;
    }
    for (; j < end; j++) {
        int s = __ldg(eidx + j);
        float nm = __ldg(enorm + j);
        uint2 u = *(const uint2*)(X + (size_t)s * 128 + (lane << 2));
        float2 pa = __half22float2(*(__half2*)&u.x), pb = __half22float2(*(__half2*)&u.y);
        a0 += pa.x * nm; a1 += pa.y * nm; a2 += pb.x * nm; a3 += pb.y * nm;
    }
    float di = __ldg(dinv + node);
    float sw = di * di;
    uint2 us = *(const uint2*)(X + (size_t)node * 128 + (lane << 2));
    float2 sa = __half22float2(*(__half2*)&us.x), sb = __half22float2(*(__half2*)&us.y);
    a0 += sa.x * sw; a1 += sa.y * sw; a2 += sb.x * sw; a3 += sb.y * sw;
    uint2 outv;
    *(__half2*)&outv.x = __floats2half2_rn(a0, a1);
    *(__half2*)&outv.y = __floats2half2_rn(a2, a3);
    *(uint2*)(Y + (size_t)node * 128 + (lane << 2)) = outv;
}

// ---------------- host launch ----------------
extern "C" void kernel_launch(void* const* d_in, const int* in_sizes, int n_in,
                              void* d_out, int out_size) {
    const float* x     = (const float*)d_in[0];
    const int*   ei    = (const int*)d_in[1];
    const float* ew    = (const float*)d_in[2];
    const float* h0    = (const float*)d_in[3];
    const float* linW  = (const float*)d_in[4];
    const float* linB  = (const float*)d_in[5];
    const float* convW = (const float*)d_in[6];
    const float* convB = (const float*)d_in[7];
    const float* Wih   = (const float*)d_in[8];
    const float* Whh   = (const float*)d_in[9];
    const float* bih   = (const float*)d_in[10];
    const float* bhh   = (const float*)d_in[11];
    const float* fcW   = (const float*)d_in[12];
    const float* fcB   = (const float*)d_in[13];
    float* out = (float*)d_out;

    const int N = in_sizes[0] / HDIM;
    const int E = in_sizes[2];
    const int C = in_sizes[13];  // 40
    const int* src = ei;
    const int* dst = ei + E;

    float *p_deg, *p_dinv, *p_enorm;
    int *p_cnt, *p_rowptr, *p_cursor, *p_bsum, *p_eidx;
    cudaGetSymbolAddress((void**)&p_deg, g_deg);
    cudaGetSymbolAddress((void**)&p_dinv, g_dinv);
    cudaGetSymbolAddress((void**)&p_cnt, g_cnt);
    cudaGetSymbolAddress((void**)&p_rowptr, g_rowptr);
    cudaGetSymbolAddress((void**)&p_cursor, g_cursor);
    cudaGetSymbolAddress((void**)&p_bsum, g_bsum);
    cudaGetSymbolAddress((void**)&p_eidx, g_eidx);
    cudaGetSymbolAddress((void**)&p_enorm, g_enorm);

    __half *p_x16, *p_act, *p_Y, *p_hA, *p_hB;
    cudaGetSymbolAddress((void**)&p_x16, g_x16);
    cudaGetSymbolAddress((void**)&p_act, g_act);
    cudaGetSymbolAddress((void**)&p_Y, g_Y);
    cudaGetSymbolAddress((void**)&p_hA, g_hA16);
    cudaGetSymbolAddress((void**)&p_hB, g_hB16);

    __half *w_lin, *w_conv, *w_ih, *w_hh, *w_fc;
    cudaGetSymbolAddress((void**)&w_lin, g_wlin);
    cudaGetSymbolAddress((void**)&w_conv, g_wconv);
    cudaGetSymbolAddress((void**)&w_ih, g_wih);
    cudaGetSymbolAddress((void**)&w_hh, g_whh);
    cudaGetSymbolAddress((void**)&w_fc, g_wfc);

    const int T = 256;
    auto cdiv = [](int a, int b) { return (a + b - 1) / b; };

    // streams/events created once (host-side objects; no device memory)
    static bool init_done = false;
    static cudaStream_t s2;
    static cudaEvent_t evFork, evAct[3], evAgg[3];
    if (!init_done) {
        cudaFuncSetAttribute(gemm_f16<1,1>, cudaFuncAttributeMaxDynamicSharedMemorySize, GEMM_SMEM);
        cudaFuncSetAttribute(gemm_f16<0,0>, cudaFuncAttributeMaxDynamicSharedMemorySize, GEMM_SMEM);
        cudaFuncSetAttribute(gru_f16, cudaFuncAttributeMaxDynamicSharedMemorySize, GRU_SMEM);
        cudaStreamCreateWithFlags(&s2, cudaStreamNonBlocking);
        cudaEventCreateWithFlags(&evFork, cudaEventDisableTiming);
        for (int i = 0; i < 3; i++) {
            cudaEventCreateWithFlags(&evAct[i], cudaEventDisableTiming);
            cudaEventCreateWithFlags(&evAgg[i], cudaEventDisableTiming);
        }
        init_done = true;
    }

    const int gy = cdiv(N, 128);   // 782
    const int gy64 = cdiv(N, 64);  // 1563

    // ---- fork: s2 runs the graph-prep chain concurrently with weight/act prep + lin ----
    cudaEventRecord(evFork, 0);
    cudaStreamWaitEvent(s2, evFork, 0);

    // s2: CSR/degree prep
    init_deg_kernel<<<cdiv(N, T), T, 0, s2>>>(p_deg, p_cnt, N);
    deg_accum_kernel<<<cdiv(E, T), T, 0, s2>>>(dst, ew, p_deg, p_cnt, E);
    dinv_kernel<<<cdiv(N, T), T, 0, s2>>>(p_deg, p_dinv, N);
    const int NB = cdiv(N, 1024);
    scan_block<<<NB, 1024, 0, s2>>>(p_cnt, p_rowptr, p_bsum, N);
    scan_tops<<<1, 32, 0, s2>>>(p_bsum, NB);
    scan_add<<<NB, 1024, 0, s2>>>(p_rowptr, p_cursor, p_bsum, N, E);
    fill_kernel<<<cdiv(E, T), T, 0, s2>>>(src, dst, ew, p_dinv, p_cursor, p_eidx, p_enorm, E);

    // stream 0: weight/activation prep + lin GEMM
    prep_weights<<<cdiv(180224, T), T>>>(linW, convW, Wih, Whh, fcW, C,
                                         w_lin, w_conv, w_ih, w_hh, w_fc);
    prep_acts<<<cdiv(N * 128, T), T>>>(x, h0, p_x16, p_hA, N * 128);
    gemm_f16<1,1><<<dim3(1, gy), 256, GEMM_SMEM>>>(p_x16, w_lin, linB, nullptr, p_act, N, 128);
    cudaEventRecord(evAct[0], 0);                    // act_0 ready

    // s2: aggregate_1(act_0) once CSR + act_0 are ready (CSR via stream order on s2)
    cudaStreamWaitEvent(s2, evAct[0], 0);
    aggregate_f16<<<cdiv(N * 32, T), T, 0, s2>>>(p_rowptr, p_eidx, p_enorm, p_act, p_dinv, p_Y, N);
    cudaEventRecord(evAgg[0], s2);

    // stream 0: GRU1 (needs act_0, hA only) runs concurrently with aggregate_1
    gru_f16<<<dim3(2, gy64), 256, GRU_SMEM>>>(p_act, p_hA, w_ih, w_hh, bih, bhh, p_hB, N);

    __half *cur = p_hB, *nxt = p_hA;

    for (int l = 0; l < 3; l++) {
        // conv_l consumes Y from aggregate_l -> wait for it
        cudaStreamWaitEvent(0, evAgg[l], 0);
        gemm_f16<1,1><<<dim3(1, gy), 256, GEMM_SMEM>>>(p_Y, w_conv + (size_t)l * 16384,
            convB + (size_t)l * HDIM, nullptr, p_act, N, 128);
        if (l < 2) {
            cudaEventRecord(evAct[l + 1], 0);        // act_{l+1} ready
            cudaStreamWaitEvent(s2, evAct[l + 1], 0);
            aggregate_f16<<<cdiv(N * 32, T), T, 0, s2>>>(p_rowptr, p_eidx, p_enorm,
                                                         p_act, p_dinv, p_Y, N);
            cudaEventRecord(evAgg[l + 1], s2);
        }
        // GRU_{l+1} concurrent with aggregate_{l+2}
        gru_f16<<<dim3(2, gy64), 256, GRU_SMEM>>>(p_act, cur, w_ih, w_hh, bih, bhh, nxt, N);
        __half* t = cur; cur = nxt; nxt = t;
    }

    // out = h @ fcW + fcB
    gemm_f16<0,0><<<dim3(1, gy), 256, GEMM_SMEM>>>(cur, w_fc, fcB, out, nullptr, N, C);
}

// round 17
// speedup vs baseline: 1.2575x; 1.0081x over previous
#include <cuda_runtime.h>
#include <cuda_fp16.h>
#include <cstdint>

#define NMAX 100000
#define EMAX 1600000
#define HDIM 128
#define G3   384

// ---------------- scratch (device globals) ----------------
__device__ float g_deg[NMAX];
__device__ float g_dinv[NMAX];
__device__ int   g_cnt[NMAX];
__device__ int   g_rowptr[NMAX + 1];
__device__ int   g_cursor[NMAX];
__device__ int   g_bsum[256];
__device__ int   g_eidx[EMAX];
__device__ float g_enorm[EMAX];

// fp16 activations (act0..act3 distinct: conv_l writes never collide with readers)
__device__ __half g_x16[(size_t)NMAX * 128];
__device__ __half g_act0[(size_t)NMAX * 128];
__device__ __half g_act1[(size_t)NMAX * 128];
__device__ __half g_act2[(size_t)NMAX * 128];
__device__ __half g_act3[(size_t)NMAX * 128];
__device__ __half g_Y[(size_t)NMAX * 128];
__device__ __half g_hA16[(size_t)NMAX * 128];
__device__ __half g_hB16[(size_t)NMAX * 128];

// fp16 weights ([rows][128] K-major = B^T)
__device__ __half g_wlin[128 * 128];
__device__ __half g_wconv[3 * 128 * 128];
__device__ __half g_wih[G3 * 128];
__device__ __half g_whh[G3 * 128];
__device__ __half g_wfc[128 * 128];

// ---------------- mma/ldmatrix helpers ----------------
__device__ __forceinline__ uint32_t smem_u32(const void* p) {
    return (uint32_t)__cvta_generic_to_shared(p);
}
__device__ __forceinline__ void ldsm_x4(uint32_t& r0, uint32_t& r1, uint32_t& r2,
                                        uint32_t& r3, uint32_t addr) {
    asm volatile("ldmatrix.sync.aligned.m8n8.x4.shared.b16 {%0,%1,%2,%3}, [%4];"
                 : "=r"(r0), "=r"(r1), "=r"(r2), "=r"(r3) : "r"(addr));
}
__device__ __forceinline__ void mma_f16(float* d, const uint32_t* a, uint32_t b0, uint32_t b1) {
    asm volatile(
        "mma.sync.aligned.m16n8k16.row.col.f32.f16.f16.f32 "
        "{%0,%1,%2,%3}, {%4,%5,%6,%7}, {%8,%9}, {%0,%1,%2,%3};"
        : "+f"(d[0]), "+f"(d[1]), "+f"(d[2]), "+f"(d[3])
        : "r"(a[0]), "r"(a[1]), "r"(a[2]), "r"(a[3]), "r"(b0), "r"(b1));
}
__device__ __forceinline__ uint32_t swz(int row, int chunk) {
    return (uint32_t)(row * 256 + ((chunk ^ (row & 7)) << 4));
}
__device__ __forceinline__ float fast_sigmoid(float x) {
    return __fdividef(1.0f, 1.0f + __expf(-x));
}
__device__ __forceinline__ float fast_tanh(float x) {
    float y;
    asm("tanh.approx.f32 %0, %1;" : "=f"(y) : "f"(x));
    return y;
}

// ---------------- graph prep kernels ----------------
__global__ void init_deg_kernel(float* __restrict__ deg, int* __restrict__ cnt, int n) {
    int i = blockIdx.x * blockDim.x + threadIdx.x;
    if (i < n) { deg[i] = 1.0f; cnt[i] = 0; }
}
__global__ void deg_accum_kernel(const int* __restrict__ dst, const float* __restrict__ ew,
                                 float* __restrict__ deg, int* __restrict__ cnt, int E) {
    int e = blockIdx.x * blockDim.x + threadIdx.x;
    if (e < E) {
        int d = dst[e];
        atomicAdd(&deg[d], ew[e]);
        atomicAdd(&cnt[d], 1);
    }
}
__global__ void dinv_kernel(const float* __restrict__ deg, float* __restrict__ dinv, int n) {
    int i = blockIdx.x * blockDim.x + threadIdx.x;
    if (i < n) {
        float d = deg[i];
        dinv[i] = (d > 0.0f) ? rsqrtf(d) : 0.0f;
    }
}
__global__ void scan_block(const int* __restrict__ cnt, int* __restrict__ out,
                           int* __restrict__ bsum, int n) {
    __shared__ int sm[1024];
    int tx = threadIdx.x;
    int gid = blockIdx.x * 1024 + tx;
    int v = (gid < n) ? cnt[gid] : 0;
    sm[tx] = v;
    __syncthreads();
    for (int off = 1; off < 1024; off <<= 1) {
        int t = (tx >= off) ? sm[tx - off] : 0;
        __syncthreads();
        sm[tx] += t;
        __syncthreads();
    }
    if (gid < n) out[gid] = sm[tx] - v;
    if (tx == 1023) bsum[blockIdx.x] = sm[1023];
}
__global__ void scan_tops(int* __restrict__ bsum, int nb) {
    if (threadIdx.x == 0) {
        int acc = 0;
        for (int i = 0; i < nb; i++) { int v = bsum[i]; bsum[i] = acc; acc += v; }
    }
}
__global__ void scan_add(int* __restrict__ rowptr, int* __restrict__ cursor,
                         const int* __restrict__ bsum, int n, int E) {
    int gid = blockIdx.x * 1024 + threadIdx.x;
    if (gid < n) {
        int v = rowptr[gid] + bsum[blockIdx.x];
        rowptr[gid] = v;
        cursor[gid] = v;
    }
    if (gid == 0) rowptr[n] = E;
}
__global__ void fill_kernel(const int* __restrict__ src, const int* __restrict__ dst,
                            const float* __restrict__ ew, const float* __restrict__ dinv,
                            int* __restrict__ cursor, int* __restrict__ eidx,
                            float* __restrict__ enorm, int E) {
    int e = blockIdx.x * blockDim.x + threadIdx.x;
    if (e >= E) return;
    int s = src[e], d = dst[e];
    float nm = dinv[s] * ew[e] * dinv[d];
    int pos = atomicAdd(&cursor[d], 1);
    eidx[pos] = s;
    enorm[pos] = nm;
}

// ---------------- consolidated converts ----------------
__global__ void prep_weights(
    const float* __restrict__ linW, const float* __restrict__ convW,
    const float* __restrict__ Wih, const float* __restrict__ Whh,
    const float* __restrict__ fcW, int C,
    __half* __restrict__ wlin, __half* __restrict__ wconv,
    __half* __restrict__ wih, __half* __restrict__ whh, __half* __restrict__ wfc)
{
    int idx = blockIdx.x * blockDim.x + threadIdx.x;
    if (idx < 16384) {
        int n = idx >> 7, k = idx & 127;
        wlin[idx] = __float2half_rn(linW[(size_t)k * 128 + n]);        // trans
    } else if (idx < 65536) {
        int i = idx - 16384;
        int l = i >> 14, r = i & 16383;
        int n = r >> 7, k = r & 127;
        wconv[i] = __float2half_rn(convW[(size_t)l * 16384 + (size_t)k * 128 + n]);
    } else if (idx < 114688) {
        int i = idx - 65536;
        wih[i] = __float2half_rn(Wih[i]);                              // no trans
    } else if (idx < 163840) {
        int i = idx - 114688;
        whh[i] = __float2half_rn(Whh[i]);
    } else if (idx < 180224) {
        int i = idx - 163840;
        int n = i >> 7, k = i & 127;
        float v = (n < C) ? fcW[(size_t)k * C + n] : 0.0f;
        wfc[i] = __float2half_rn(v);
    }
}
__global__ void prep_acts(const float* __restrict__ x, const float* __restrict__ h0,
                          __half* __restrict__ x16, __half* __restrict__ hA, int n) {
    int i = blockIdx.x * blockDim.x + threadIdx.x;
    if (i < n) {
        x16[i] = __float2half_rn(x[i]);
        hA[i] = __float2half_rn(h0[i]);
    }
}

// ---------------- fp16 GEMM: C[M,Nc] = A[M,128] @ B^T (+bias)(+relu) ----------------
#define GF_A 0
#define GF_B 32768
#define GEMM_SMEM 65536

template <int RELU, int OUT>   // OUT: 0 = fp32 C[M,Nc], 1 = fp16 act[M,128]
__global__ __launch_bounds__(256, 2) void gemm_f16(
    const __half* __restrict__ A, const __half* __restrict__ B,
    const float* __restrict__ bias,
    float* __restrict__ C, __half* __restrict__ Cact,
    int M, int Nc)
{
    extern __shared__ char sm[];
    __shared__ float s_bias[128];
    const uint32_t smb = smem_u32(sm);
    const int tid = threadIdx.x;
    const int lane = tid & 31;
    const int wid = tid >> 5;
    const int m0 = blockIdx.y << 7;
    const int n0 = blockIdx.x << 7;

    for (int i = tid; i < 2048; i += 256) {
        int r = i >> 4, c = i & 15;
        uint4 v = make_uint4(0, 0, 0, 0);
        if (m0 + r < M) v = *(const uint4*)(A + (size_t)(m0 + r) * 128 + c * 8);
        *(uint4*)(sm + GF_A + swz(r, c)) = v;
    }
    for (int i = tid; i < 2048; i += 256) {
        int r = i >> 4, c = i & 15;
        uint4 v = *(const uint4*)(B + (size_t)(n0 + r) * 128 + c * 8);
        *(uint4*)(sm + GF_B + swz(r, c)) = v;
    }
    if (tid < 128) {
        int gn = n0 + tid;
        s_bias[tid] = (bias && gn < Nc) ? bias[gn] : 0.0f;
    }
    __syncthreads();

    const int wm = (wid >> 2) << 6;
    const int wn = (wid & 3) << 5;

    float acc[4][4][4];
#pragma unroll
    for (int i = 0; i < 4; i++)
#pragma unroll
        for (int j = 0; j < 4; j++)
#pragma unroll
            for (int k = 0; k < 4; k++) acc[i][j][k] = 0.0f;

#pragma unroll
    for (int kk = 0; kk < 8; kk++) {
        uint32_t bfr[2][4];
#pragma unroll
        for (int np = 0; np < 2; np++) {
            int row = wn + np * 16 + (lane & 15);
            int chunk = kk * 2 + (lane >> 4);
            ldsm_x4(bfr[np][0], bfr[np][1], bfr[np][2], bfr[np][3],
                    smb + GF_B + swz(row, chunk));
        }
#pragma unroll
        for (int mf = 0; mf < 4; mf++) {
            int row = wm + mf * 16 + (lane & 15);
            int chunk = kk * 2 + (lane >> 4);
            uint32_t a[4];
            ldsm_x4(a[0], a[1], a[2], a[3], smb + GF_A + swz(row, chunk));
#pragma unroll
            for (int nf = 0; nf < 4; nf++) {
                uint32_t b0 = bfr[nf >> 1][nf & 1];
                uint32_t b1 = bfr[nf >> 1][2 + (nf & 1)];
                mma_f16(acc[mf][nf], a, b0, b1);
            }
        }
    }

    const int gr = lane >> 2, gc = lane & 3;
#pragma unroll
    for (int mf = 0; mf < 4; mf++) {
#pragma unroll
        for (int i2 = 0; i2 < 2; i2++) {
            int r0 = m0 + wm + mf * 16 + gr + i2 * 8;
            if (r0 >= M) continue;
#pragma unroll
            for (int nf = 0; nf < 4; nf++) {
                int cl = wn + nf * 8 + (gc << 1);
                int col = n0 + cl;
                float v0 = acc[mf][nf][i2 * 2 + 0] + s_bias[cl];
                float v1 = acc[mf][nf][i2 * 2 + 1] + s_bias[cl + 1];
                if (RELU) { v0 = fmaxf(v0, 0.f); v1 = fmaxf(v1, 0.f); }
                if (OUT == 0) {
                    if (col < Nc) {
                        if (col + 1 < Nc)
                            *(float2*)(C + (size_t)r0 * Nc + col) = make_float2(v0, v1);
                        else
                            C[(size_t)r0 * Nc + col] = v0;
                    }
                } else {
                    *(__half2*)(Cact + (size_t)r0 * 128 + col) = __floats2half2_rn(v0, v1);
                }
            }
        }
    }
}

// ---------------- fused GRU fp16, 2-phase (validated) ----------------
#define GR_X 0
#define GR_P 16384
#define GR_W 32768
#define GRU_SMEM 81920

__global__ __launch_bounds__(256, 2) void gru_f16(
    const __half* __restrict__ X, const __half* __restrict__ P,
    const __half* __restrict__ Wih, const __half* __restrict__ Whh,
    const float* __restrict__ bih, const float* __restrict__ bhh,
    __half* __restrict__ O, int M)
{
    extern __shared__ char sm[];
    __shared__ float s_brz[128], s_bin[64], s_bhn[64];
    const uint32_t smb = smem_u32(sm);
    const int tid = threadIdx.x;
    const int lane = tid & 31;
    const int wid = tid >> 5;
    const int m0 = blockIdx.y << 6;
    const int n0 = blockIdx.x << 6;

    for (int i = tid; i < 1024; i += 256) {
        int r = i >> 4, c = i & 15;
        uint4 xv = make_uint4(0, 0, 0, 0), pv = xv;
        if (m0 + r < M) {
            xv = *(const uint4*)(X + (size_t)(m0 + r) * 128 + c * 8);
            pv = *(const uint4*)(P + (size_t)(m0 + r) * 128 + c * 8);
        }
        uint32_t off = swz(r, c);
        *(uint4*)(sm + GR_X + off) = xv;
        *(uint4*)(sm + GR_P + off) = pv;
    }
    if (tid < 128) {
        int g = tid >> 6, c = tid & 63;
        s_brz[tid] = bih[g * 128 + n0 + c] + bhh[g * 128 + n0 + c];
    } else if (tid < 192) {
        int c = tid - 128;
        s_bin[c] = bih[256 + n0 + c];
        s_bhn[c] = bhh[256 + n0 + c];
    }

    const int wm = (wid & 1) << 5;
    const int wn = (wid >> 1) << 4;

    float acc[4][2][2][4];
#pragma unroll
    for (int s = 0; s < 4; s++)
#pragma unroll
        for (int i = 0; i < 2; i++)
#pragma unroll
            for (int j = 0; j < 2; j++)
#pragma unroll
                for (int k = 0; k < 4; k++) acc[s][i][j][k] = 0.0f;

#pragma unroll
    for (int ph = 0; ph < 2; ph++) {
        const __half* W = ph ? Whh : Wih;
        const uint32_t aP = ph ? GR_P : GR_X;

        __syncthreads();
        for (int i = tid; i < 3072; i += 256) {
            int g = i >> 10;
            int r = (i >> 4) & 63;
            int c = i & 15;
            int grow = g * 128 + n0 + r;
            uint4 v = *(const uint4*)(W + (size_t)grow * 128 + c * 8);
            *(uint4*)(sm + GR_W + g * 16384 + swz(r, c)) = v;
        }
        __syncthreads();

#pragma unroll
        for (int kk = 0; kk < 8; kk++) {
            uint32_t bfr[3][4];
#pragma unroll
            for (int g = 0; g < 3; g++) {
                int row = wn + (lane & 15);
                int chunk = kk * 2 + (lane >> 4);
                ldsm_x4(bfr[g][0], bfr[g][1], bfr[g][2], bfr[g][3],
                        smb + GR_W + g * 16384 + swz(row, chunk));
            }
#pragma unroll
            for (int mf = 0; mf < 2; mf++) {
                int row = wm + mf * 16 + (lane & 15);
                int chunk = kk * 2 + (lane >> 4);
                uint32_t a[4];
                ldsm_x4(a[0], a[1], a[2], a[3], smb + aP + swz(row, chunk));
#pragma unroll
                for (int g = 0; g < 3; g++) {
                    int slot = (g < 2) ? g : (2 + ph);
#pragma unroll
                    for (int nf = 0; nf < 2; nf++)
                        mma_f16(acc[slot][mf][nf], a, bfr[g][nf], bfr[g][2 + nf]);
                }
            }
        }
    }

    const int gr = lane >> 2, gc = lane & 3;
#pragma unroll
    for (int mf = 0; mf < 2; mf++) {
#pragma unroll
        for (int i2 = 0; i2 < 2; i2++) {
            int lrow = wm + mf * 16 + gr + i2 * 8;
            int row = m0 + lrow;
            if (row >= M) continue;
#pragma unroll
            for (int nf = 0; nf < 2; nf++) {
                int cl = wn + nf * 8 + (gc << 1);
                int gcol = n0 + cl;
                float rr0 = acc[0][mf][nf][i2 * 2 + 0] + s_brz[cl];
                float rr1 = acc[0][mf][nf][i2 * 2 + 1] + s_brz[cl + 1];
                float zz0 = acc[1][mf][nf][i2 * 2 + 0] + s_brz[64 + cl];
                float zz1 = acc[1][mf][nf][i2 * 2 + 1] + s_brz[64 + cl + 1];
                float in0 = acc[2][mf][nf][i2 * 2 + 0] + s_bin[cl];
                float in1 = acc[2][mf][nf][i2 * 2 + 1] + s_bin[cl + 1];
                float hn0 = acc[3][mf][nf][i2 * 2 + 0] + s_bhn[cl];
                float hn1 = acc[3][mf][nf][i2 * 2 + 1] + s_bhn[cl + 1];
                uint32_t poff = swz(lrow, gcol >> 3) + (gcol & 7) * 2;
                __half2 hp2 = *(__half2*)(sm + GR_P + poff);
                float hp0 = __low2float(hp2), hp1 = __high2float(hp2);
                float r0 = fast_sigmoid(rr0);
                float r1 = fast_sigmoid(rr1);
                float z0 = fast_sigmoid(zz0);
                float z1 = fast_sigmoid(zz1);
                float n0v = fast_tanh(in0 + r0 * hn0);
                float n1v = fast_tanh(in1 + r1 * hn1);
                float h0 = (1.0f - z0) * n0v + z0 * hp0;
                float h1 = (1.0f - z1) * n1v + z1 * hp1;
                *(__half2*)(O + (size_t)row * 128 + gcol) = __floats2half2_rn(h0, h1);
            }
        }
    }
}

// ---------------- CSR gather aggregation on fp16 activations ----------------
__global__ __launch_bounds__(256) void aggregate_f16(
    const int* __restrict__ rowptr, const int* __restrict__ eidx,
    const float* __restrict__ enorm, const __half* __restrict__ X,
    const float* __restrict__ dinv, __half* __restrict__ Y, int N)
{
    int node = (int)(((size_t)blockIdx.x * blockDim.x + threadIdx.x) >> 5);
    if (node >= N) return;
    int lane = threadIdx.x & 31;
    int start = __ldg(rowptr + node);
    int end = __ldg(rowptr + node + 1);
    float a0 = 0.f, a1 = 0.f, a2 = 0.f, a3 = 0.f;
    int j = start;
    for (; j + 4 <= end; j += 4) {
        int s0 = __ldg(eidx + j);
        int s1 = __ldg(eidx + j + 1);
        int s2 = __ldg(eidx + j + 2);
        int s3 = __ldg(eidx + j + 3);
        float n0 = __ldg(enorm + j);
        float n1 = __ldg(enorm + j + 1);
        float n2 = __ldg(enorm + j + 2);
        float n3 = __ldg(enorm + j + 3);
        uint2 u0 = *(const uint2*)(X + (size_t)s0 * 128 + (lane << 2));
        uint2 u1 = *(const uint2*)(X + (size_t)s1 * 128 + (lane << 2));
        uint2 u2 = *(const uint2*)(X + (size_t)s2 * 128 + (lane << 2));
        uint2 u3 = *(const uint2*)(X + (size_t)s3 * 128 + (lane << 2));
        float2 p0a = __half22float2(*(__half2*)&u0.x), p0b = __half22float2(*(__half2*)&u0.y);
        float2 p1a = __half22float2(*(__half2*)&u1.x), p1b = __half22float2(*(__half2*)&u1.y);
        float2 p2a = __half22float2(*(__half2*)&u2.x), p2b = __half22float2(*(__half2*)&u2.y);
        float2 p3a = __half22float2(*(__half2*)&u3.x), p3b = __half22float2(*(__half2*)&u3.y);
        a0 += p0a.x * n0 + p1a.x * n1 + p2a.x * n2 + p3a.x * n3;
        a1 += p0a.y * n0 + p1a.y * n1 + p2a.y * n2 + p3a.y * n3;
        a2 += p0b.x * n0 + p1b.x * n1 + p2b.x * n2 + p3b.x * n3;
        a3 += p0b.y * n0 + p1b.y * n1 + p2b.y * n2 + p3b.y * n3;
    }
    for (; j < end; j++) {
        int s = __ldg(eidx + j);
        float nm = __ldg(enorm + j);
        uint2 u = *(const uint2*)(X + (size_t)s * 128 + (lane << 2));
        float2 pa = __half22float2(*(__half2*)&u.x), pb = __half22float2(*(__half2*)&u.y);
        a0 += pa.x * nm; a1 += pa.y * nm; a2 += pb.x * nm; a3 += pb.y * nm;
    }
    float di = __ldg(dinv + node);
    float sw = di * di;
    uint2 us = *(const uint2*)(X + (size_t)node * 128 + (lane << 2));
    float2 sa = __half22float2(*(__half2*)&us.x), sb = __half22float2(*(__half2*)&us.y);
    a0 += sa.x * sw; a1 += sa.y * sw; a2 += sb.x * sw; a3 += sb.y * sw;
    uint2 outv;
    *(__half2*)&outv.x = __floats2half2_rn(a0, a1);
    *(__half2*)&outv.y = __floats2half2_rn(a2, a3);
    *(uint2*)(Y + (size_t)node * 128 + (lane << 2)) = outv;
}

// ---------------- host launch ----------------
extern "C" void kernel_launch(void* const* d_in, const int* in_sizes, int n_in,
                              void* d_out, int out_size) {
    const float* x     = (const float*)d_in[0];
    const int*   ei    = (const int*)d_in[1];
    const float* ew    = (const float*)d_in[2];
    const float* h0    = (const float*)d_in[3];
    const float* linW  = (const float*)d_in[4];
    const float* linB  = (const float*)d_in[5];
    const float* convW = (const float*)d_in[6];
    const float* convB = (const float*)d_in[7];
    const float* Wih   = (const float*)d_in[8];
    const float* Whh   = (const float*)d_in[9];
    const float* bih   = (const float*)d_in[10];
    const float* bhh   = (const float*)d_in[11];
    const float* fcW   = (const float*)d_in[12];
    const float* fcB   = (const float*)d_in[13];
    float* out = (float*)d_out;

    const int N = in_sizes[0] / HDIM;
    const int E = in_sizes[2];
    const int C = in_sizes[13];  // 40
    const int* src = ei;
    const int* dst = ei + E;

    float *p_deg, *p_dinv, *p_enorm;
    int *p_cnt, *p_rowptr, *p_cursor, *p_bsum, *p_eidx;
    cudaGetSymbolAddress((void**)&p_deg, g_deg);
    cudaGetSymbolAddress((void**)&p_dinv, g_dinv);
    cudaGetSymbolAddress((void**)&p_cnt, g_cnt);
    cudaGetSymbolAddress((void**)&p_rowptr, g_rowptr);
    cudaGetSymbolAddress((void**)&p_cursor, g_cursor);
    cudaGetSymbolAddress((void**)&p_bsum, g_bsum);
    cudaGetSymbolAddress((void**)&p_eidx, g_eidx);
    cudaGetSymbolAddress((void**)&p_enorm, g_enorm);

    __half *p_x16, *p_Y, *p_hA, *p_hB;
    __half *p_act[4];
    cudaGetSymbolAddress((void**)&p_x16, g_x16);
    cudaGetSymbolAddress((void**)&p_act[0], g_act0);
    cudaGetSymbolAddress((void**)&p_act[1], g_act1);
    cudaGetSymbolAddress((void**)&p_act[2], g_act2);
    cudaGetSymbolAddress((void**)&p_act[3], g_act3);
    cudaGetSymbolAddress((void**)&p_Y, g_Y);
    cudaGetSymbolAddress((void**)&p_hA, g_hA16);
    cudaGetSymbolAddress((void**)&p_hB, g_hB16);

    __half *w_lin, *w_conv, *w_ih, *w_hh, *w_fc;
    cudaGetSymbolAddress((void**)&w_lin, g_wlin);
    cudaGetSymbolAddress((void**)&w_conv, g_wconv);
    cudaGetSymbolAddress((void**)&w_ih, g_wih);
    cudaGetSymbolAddress((void**)&w_hh, g_whh);
    cudaGetSymbolAddress((void**)&w_fc, g_wfc);

    const int T = 256;
    auto cdiv = [](int a, int b) { return (a + b - 1) / b; };

    static bool init_done = false;
    static cudaStream_t s2;
    static cudaEvent_t evFork, evAct0, evConv[3];
    if (!init_done) {
        cudaFuncSetAttribute(gemm_f16<1,1>, cudaFuncAttributeMaxDynamicSharedMemorySize, GEMM_SMEM);
        cudaFuncSetAttribute(gemm_f16<0,0>, cudaFuncAttributeMaxDynamicSharedMemorySize, GEMM_SMEM);
        cudaFuncSetAttribute(gru_f16, cudaFuncAttributeMaxDynamicSharedMemorySize, GRU_SMEM);
        cudaStreamCreateWithFlags(&s2, cudaStreamNonBlocking);
        cudaEventCreateWithFlags(&evFork, cudaEventDisableTiming);
        cudaEventCreateWithFlags(&evAct0, cudaEventDisableTiming);
        for (int i = 0; i < 3; i++)
            cudaEventCreateWithFlags(&evConv[i], cudaEventDisableTiming);
        init_done = true;
    }

    const int gy = cdiv(N, 128);   // 782
    const int gy64 = cdiv(N, 64);  // 1563

    // ---- fork: s2 runs CSR prep + all aggregate/conv pairs ----
    cudaEventRecord(evFork, 0);
    cudaStreamWaitEvent(s2, evFork, 0);

    // s2: CSR/degree prep
    init_deg_kernel<<<cdiv(N, T), T, 0, s2>>>(p_deg, p_cnt, N);
    deg_accum_kernel<<<cdiv(E, T), T, 0, s2>>>(dst, ew, p_deg, p_cnt, E);
    dinv_kernel<<<cdiv(N, T), T, 0, s2>>>(p_deg, p_dinv, N);
    const int NB = cdiv(N, 1024);
    scan_block<<<NB, 1024, 0, s2>>>(p_cnt, p_rowptr, p_bsum, N);
    scan_tops<<<1, 32, 0, s2>>>(p_bsum, NB);
    scan_add<<<NB, 1024, 0, s2>>>(p_rowptr, p_cursor, p_bsum, N, E);
    fill_kernel<<<cdiv(E, T), T, 0, s2>>>(src, dst, ew, p_dinv, p_cursor, p_eidx, p_enorm, E);

    // stream 0: weight/activation prep + lin GEMM -> act0
    prep_weights<<<cdiv(180224, T), T>>>(linW, convW, Wih, Whh, fcW, C,
                                         w_lin, w_conv, w_ih, w_hh, w_fc);
    prep_acts<<<cdiv(N * 128, T), T>>>(x, h0, p_x16, p_hA, N * 128);
    gemm_f16<1,1><<<dim3(1, gy), 256, GEMM_SMEM>>>(p_x16, w_lin, linB, nullptr, p_act[0], N, 128);
    cudaEventRecord(evAct0, 0);

    // s2: for each layer: aggregate(act_l) -> Y; conv -> act_{l+1}  (all serial on s2)
    cudaStreamWaitEvent(s2, evAct0, 0);
    for (int l = 0; l < 3; l++) {
        aggregate_f16<<<cdiv(N * 32, T), T, 0, s2>>>(p_rowptr, p_eidx, p_enorm,
                                                     p_act[l], p_dinv, p_Y, N);
        gemm_f16<1,1><<<dim3(1, gy), 256, GEMM_SMEM, s2>>>(p_Y, w_conv + (size_t)l * 16384,
            convB + (size_t)l * HDIM, nullptr, p_act[l + 1], N, 128);
        cudaEventRecord(evConv[l], s2);
    }

    // stream 0: GRU chain (GRU_{l+1} waits conv_l output)
    gru_f16<<<dim3(2, gy64), 256, GRU_SMEM>>>(p_act[0], p_hA, w_ih, w_hh, bih, bhh, p_hB, N);
    __half *cur = p_hB, *nxt = p_hA;
    for (int l = 0; l < 3; l++) {
        cudaStreamWaitEvent(0, evConv[l], 0);
        gru_f16<<<dim3(2, gy64), 256, GRU_SMEM>>>(p_act[l + 1], cur, w_ih, w_hh, bih, bhh, nxt, N);
        __half* t = cur; cur = nxt; nxt = t;
    }

    // out = h @ fcW + fcB
    gemm_f16<0,0><<<dim3(1, gy), 256, GEMM_SMEM>>>(cur, w_fc, fcB, out, nullptr, N, C);
}